// round 11
// baseline (speedup 1.0000x reference)
#include <cuda_runtime.h>
#include <cuda_bf16.h>
#include <math.h>
#include <cstdint>

// ---------------------------------------------------------------------------
// Problem constants
// ---------------------------------------------------------------------------
#define NN 64
#define CC 2048
#define HH 24
#define WW 12
#define PP 5
#define CLK 256
#define HW  (HH*WW)      // 288
#define PC  (PP*CLK)     // 1280
#define CM  (CC+PC)      // 3328
#define KSL 32           // split-K local  (kchunk 64, 1 stage)
#define KSM 26           // split-K merge  (kchunk 128, 2 stages)
#define BN_EPS 1e-5f

// ---------------------------------------------------------------------------
// Scratch
// ---------------------------------------------------------------------------
__device__ float g_avg[PP*NN*CC];
__device__ float g_cat[NN*CM];
__device__ float g_lpart[KSL*NN*PC];
__device__ float g_mpart[KSM*NN*CC];
__device__ float g_ss[NN*4];

// ---------------------------------------------------------------------------
// PTX helpers (baseline instructions only; NO tcgen05)
// ---------------------------------------------------------------------------
__device__ __forceinline__ uint32_t smem_u32(const void* p) {
    uint32_t a;
    asm("{ .reg .u64 t; cvta.to.shared.u64 t, %1; cvt.u32.u64 %0, t; }" : "=r"(a) : "l"(p));
    return a;
}
__device__ __forceinline__ void ldsm4(uint32_t* r, uint32_t addr) {
    asm volatile("ldmatrix.sync.aligned.m8n8.x4.shared.b16 {%0,%1,%2,%3}, [%4];"
        : "=r"(r[0]), "=r"(r[1]), "=r"(r[2]), "=r"(r[3]) : "r"(addr));
}
__device__ __forceinline__ void mma_bf16(float* d, const uint32_t* a,
                                         uint32_t b0, uint32_t b1) {
    asm volatile(
        "mma.sync.aligned.m16n8k16.row.col.f32.bf16.bf16.f32 "
        "{%0,%1,%2,%3}, {%4,%5,%6,%7}, {%8,%9}, {%0,%1,%2,%3};"
        : "+f"(d[0]), "+f"(d[1]), "+f"(d[2]), "+f"(d[3])
        : "r"(a[0]), "r"(a[1]), "r"(a[2]), "r"(a[3]), "r"(b0), "r"(b1));
}
// pack two fp32 -> bf16x2 (lo in low half, hi in high half), round-to-nearest
__device__ __forceinline__ uint32_t cvt2(float lo, float hi) {
    uint32_t r;
    asm("cvt.rn.bf16x2.f32 %0, %1, %2;" : "=r"(r) : "f"(hi), "f"(lo));
    return r;
}
// residual pair given packed hi pair
__device__ __forceinline__ uint32_t resid2(uint32_t hpack, float lo, float hi) {
    float rlo = lo - __uint_as_float(hpack << 16);
    float rhi = hi - __uint_as_float(hpack & 0xFFFF0000u);
    return cvt2(rlo, rhi);
}
// fp32 -> bf16 hi/lo split of 8 contiguous values; 16B store per plane at sw.
__device__ __forceinline__ void cvt_store8(const float* __restrict__ src,
                                           char* hip, char* lop, uint32_t sw)
{
    float4 f0 = *(const float4*)src;
    float4 f1 = *(const float4*)(src + 4);
    uint4 vh, vl;
    vh.x = cvt2(f0.x, f0.y);  vl.x = resid2(vh.x, f0.x, f0.y);
    vh.y = cvt2(f0.z, f0.w);  vl.y = resid2(vh.y, f0.z, f0.w);
    vh.z = cvt2(f1.x, f1.y);  vl.z = resid2(vh.z, f1.x, f1.y);
    vh.w = cvt2(f1.z, f1.w);  vl.w = resid2(vh.w, f1.z, f1.w);
    *(uint4*)(hip + sw) = vh;
    *(uint4*)(lop + sw) = vl;
}

// ---------------------------------------------------------------------------
// Kernel 1: fused boxes + pooling + global max.
// Lane owns hw = 4*lane + {0..3} at bases {0, 128, 256(lane<8)}: LDG.128 x3
// per channel. smem-transpose reduction (stride-25, conflict-free).
// grid = (8 ctiles, 64 n), 256 threads
// ---------------------------------------------------------------------------
__global__ __launch_bounds__(256) void pool_kernel(const float* __restrict__ x,
                                                   const float* __restrict__ poses)
{
    int n   = blockIdx.y;
    int c0  = blockIdx.x * 256;
    int tid = threadIdx.x, warp = tid >> 5, lane = tid & 31;

    __shared__ int   s_box[PP][4];
    __shared__ float s_inv[PP];
    __shared__ float s_avg[PP][256];
    __shared__ float s_max[256];
    __shared__ float s_red[8][32][25];

    if (tid < PP) {
        int p = tid;
        const float* kp = poses + ((long long)n*17 + p*4)*4;
        float kx = kp[0], ky = kp[1], kz = kp[2];
        float bx  = fminf(fmaxf(kx - 0.25f, 0.0f), 0.75f) * kz;
        float by  = fminf(fmaxf(ky - 0.25f, 0.0f), 0.75f) * kz;
        float bwh = 0.5f * kz;
        int xs = max(0,      (int)rintf((float)WW * bx));
        int xe = min(WW - 1, (int)rintf((float)WW * (bx + bwh)));
        int ys = max(0,      (int)rintf((float)HH * by));
        int ye = min(HH - 1, (int)rintf((float)HH * (by + bwh)));
        s_box[p][0] = xs; s_box[p][1] = xe; s_box[p][2] = ys; s_box[p][3] = ye;
        int area = (ye - ys) * (xe - xs);
        s_inv[p] = (area > 0) ? (1.0f / (float)area) : 1.0f;
    }
    __syncthreads();

    // 12 per-lane masks for hw = base + 4*lane + j, base in {0,128,256}
    unsigned mk[12];
    #pragma unroll
    for (int t = 0; t < 3; ++t) {
        #pragma unroll
        for (int j = 0; j < 4; ++j) {
            int hw = t*128 + 4*lane + j;
            unsigned m = 0;
            if (hw < HW) {
                int h = hw / WW, w = hw % WW;
                #pragma unroll
                for (int p = 0; p < PP; ++p) {
                    bool in = (h >= s_box[p][2]) && (h < s_box[p][3]) &&
                              (w >= s_box[p][0]) && (w < s_box[p][1]);
                    if (in) m |= (1u << p);
                }
            }
            mk[t*4+j] = m;
        }
    }
    bool tailok = (lane < 8);

    #pragma unroll 1
    for (int g = 0; g < 8; ++g) {
        int c = c0 + warp*32 + g*4;
        const float* b = x + ((size_t)(n*CC + c))*HW;
        float v[4][12];
        #pragma unroll
        for (int q = 0; q < 4; ++q) {
            float4 va = *(const float4*)(b + (size_t)q*HW + 4*lane);
            float4 vb = *(const float4*)(b + (size_t)q*HW + 128 + 4*lane);
            float4 vc = make_float4(-3.4e38f, -3.4e38f, -3.4e38f, -3.4e38f);
            if (tailok) vc = *(const float4*)(b + (size_t)q*HW + 256 + 4*lane);
            v[q][0]=va.x; v[q][1]=va.y; v[q][2]=va.z;  v[q][3]=va.w;
            v[q][4]=vb.x; v[q][5]=vb.y; v[q][6]=vb.z;  v[q][7]=vb.w;
            v[q][8]=vc.x; v[q][9]=vc.y; v[q][10]=vc.z; v[q][11]=vc.w;
        }

        float s[4][PP];
        float mx[4];
        #pragma unroll
        for (int q = 0; q < 4; ++q) {
            mx[q] = -3.402823466e38f;
            #pragma unroll
            for (int p = 0; p < PP; ++p) s[q][p] = 0.f;
        }
        #pragma unroll
        for (int k = 0; k < 12; ++k) {
            unsigned m = mk[k];
            #pragma unroll
            for (int q = 0; q < 4; ++q) mx[q] = fmaxf(mx[q], v[q][k]);
            #pragma unroll
            for (int p = 0; p < PP; ++p) {
                if (m & (1u << p)) {
                    s[0][p] += v[0][k]; s[1][p] += v[1][k];
                    s[2][p] += v[2][k]; s[3][p] += v[3][k];
                }
            }
        }
        // smem transpose reduce
        #pragma unroll
        for (int q = 0; q < 4; ++q) {
            #pragma unroll
            for (int p = 0; p < PP; ++p) s_red[warp][lane][q*6 + p] = s[q][p];
            s_red[warp][lane][q*6 + 5] = mx[q];
        }
        __syncwarp();
        if (lane < 24) {
            int q = lane / 6, r = lane - q*6;
            int ch = warp*32 + g*4 + q;
            if (r < 5) {
                float a0 = 0.f, a1 = 0.f, a2 = 0.f, a3 = 0.f;
                #pragma unroll
                for (int l = 0; l < 32; l += 4) {
                    a0 += s_red[warp][l+0][lane];
                    a1 += s_red[warp][l+1][lane];
                    a2 += s_red[warp][l+2][lane];
                    a3 += s_red[warp][l+3][lane];
                }
                s_avg[r][ch] = (a0 + a1) + (a2 + a3);
            } else {
                float m0 = s_red[warp][0][lane];
                #pragma unroll
                for (int l = 1; l < 32; ++l) m0 = fmaxf(m0, s_red[warp][l][lane]);
                s_max[ch] = m0;
            }
        }
        __syncwarp();
    }
    __syncthreads();
    int c = c0 + tid;
    #pragma unroll
    for (int p = 0; p < PP; ++p)
        g_avg[((size_t)p*NN + n)*CC + c] = s_avg[p][tid] * s_inv[p];
    g_cat[n*CM + PC + c] = s_max[tid];
}

// ---------------------------------------------------------------------------
// Kernel 2: warp-MMA bf16x3 split-K GEMM.
// Block 64x128, 8 warps (16x64 per warp). 3 CTAs/SM forced via launch bounds.
// MODE 0: local grid (10, 32), 1 stage.  MODE 1: merge grid (16, 26), 2 stages.
// ---------------------------------------------------------------------------
#define SMEMG (49152 + 1024)

template<int MODE>
__global__ __launch_bounds__(256, 3) void wgemm(const float* __restrict__ Bw)
{
    constexpr int LDAB = MODE ? CM : CC;
    constexpr int NTOT = MODE ? CC : PC;
    constexpr int KSg  = MODE ? KSM : KSL;
    constexpr int KCH  = (MODE ? CM : CC) / KSg;   // 128 / 64
    constexpr int NST  = KCH / 64;                 // 2 / 1

    extern __shared__ char smraw[];
    uint32_t rawu  = smem_u32(smraw);
    uint32_t sbase = (rawu + 127) & ~127u;
    char* sm = smraw + (sbase - rawu);

    int tid = threadIdx.x, wid = tid >> 5, lane = tid & 31;
    int ct = blockIdx.x, ks = blockIdx.y;

    const float* Ab = MODE ? g_cat : (g_avg + (size_t)(ct >> 1) * NN * CC);
    const float* Bb = Bw + (size_t)ct * 128 * LDAB;
    float* Cp = MODE ? g_mpart : g_lpart;
    int colbase = ct * 128;

    int r0  = (wid & 3) * 16;
    int c0w = (wid >> 2) * 64;

    int aRow = r0 + (lane & 15);
    uint32_t aOffBase = (uint32_t)aRow * 128;
    uint32_t aRot     = (uint32_t)(aRow & 7) << 4;
    uint32_t aK       = (uint32_t)(lane >> 4) * 16;
    int bnrel         = (lane & 7) + ((lane >> 4) << 3);
    uint32_t bK       = (uint32_t)((lane >> 3) & 1) * 16;

    float acc[8][4];
    #pragma unroll
    for (int t = 0; t < 8; ++t) { acc[t][0]=acc[t][1]=acc[t][2]=acc[t][3]=0.f; }

    int kbeg = ks * KCH;
    #pragma unroll 1
    for (int st = 0; st < NST; ++st) {
        int k0 = kbeg + st * 64;
        #pragma unroll
        for (int i = 0; i < 2; ++i) {
            int g = tid + i * 256;
            int r = g >> 3, c = (g & 7) * 8;
            uint32_t off = (uint32_t)r*128 + (((uint32_t)c*2) ^ (((uint32_t)(r&7))<<4));
            cvt_store8(Ab + (size_t)r*LDAB + k0 + c, sm, sm + 8192, off);
        }
        #pragma unroll
        for (int i = 0; i < 4; ++i) {
            int g = tid + i * 256;
            int r = g >> 3, c = (g & 7) * 8;
            uint32_t off = (uint32_t)r*128 + (((uint32_t)c*2) ^ (((uint32_t)(r&7))<<4));
            cvt_store8(Bb + (size_t)r*LDAB + k0 + c, sm + 16384, sm + 32768, off);
        }
        __syncthreads();

        #pragma unroll
        for (int kk = 0; kk < 4; ++kk) {
            uint32_t k2 = (uint32_t)kk * 32;
            uint32_t aoff = aOffBase + ((k2 + aK) ^ aRot);
            uint32_t Ahi[4], Alo[4];
            ldsm4(Ahi, sbase + aoff);
            ldsm4(Alo, sbase + 8192 + aoff);
            #pragma unroll
            for (int gq = 0; gq < 4; ++gq) {
                int brow = c0w + gq*16 + bnrel;
                uint32_t boff = (uint32_t)brow*128 +
                                ((k2 + bK) ^ (((uint32_t)(brow & 7)) << 4));
                uint32_t Bh[4], Bl[4];
                ldsm4(Bh, sbase + 16384 + boff);
                ldsm4(Bl, sbase + 32768 + boff);
                #pragma unroll
                for (int hf = 0; hf < 2; ++hf) {
                    float* d = acc[gq*2 + hf];
                    mma_bf16(d, Ahi, Bh[hf*2], Bh[hf*2+1]);
                    mma_bf16(d, Ahi, Bl[hf*2], Bl[hf*2+1]);
                    mma_bf16(d, Alo, Bh[hf*2], Bh[hf*2+1]);
                }
            }
        }
        if (st + 1 < NST) __syncthreads();
    }

    int grow = lane >> 2, gcol = (lane & 3) * 2;
    #pragma unroll
    for (int t = 0; t < 8; ++t) {
        int col = colbase + c0w + t*8 + gcol;
        size_t idx0 = ((size_t)ks*NN + r0 + grow) * NTOT + col;
        size_t idx1 = idx0 + (size_t)8 * NTOT;
        *(float2*)&Cp[idx0] = make_float2(acc[t][0], acc[t][1]);
        *(float2*)&Cp[idx1] = make_float2(acc[t][2], acc[t][3]);
    }
}

// ---------------------------------------------------------------------------
// Kernel 3: local epilogue, 4-way ks-split (8 each) + smem combine.
// grid = 320 x 256
// ---------------------------------------------------------------------------
__global__ __launch_bounds__(256) void epi_local(
    const float* __restrict__ lb,   const float* __restrict__ lgam,
    const float* __restrict__ lbet, const float* __restrict__ lmean,
    const float* __restrict__ lvar)
{
    int tid  = threadIdx.x;
    int out  = tid & 63;
    int part = tid >> 6;                     // 0..3 -> ks 8*part..+7
    int e4   = blockIdx.x * 64 + out;
    int nrow = e4 / (PC/4);
    int c4   = (e4 - nrow*(PC/4)) * 4;

    float4 a = make_float4(0.f, 0.f, 0.f, 0.f);
    #pragma unroll
    for (int i = 0; i < 8; ++i) {
        int ks = part*8 + i;
        float4 t = *(const float4*)&g_lpart[((size_t)ks*NN + nrow)*PC + c4];
        a.x += t.x; a.y += t.y; a.z += t.z; a.w += t.w;
    }
    __shared__ float4 sred[4][64];
    sred[part][out] = a;
    __syncthreads();
    if (tid < 64) {
        float4 a0 = sred[0][tid], a1 = sred[1][tid], a2 = sred[2][tid], a3 = sred[3][tid];
        a.x = (a0.x + a1.x) + (a2.x + a3.x);
        a.y = (a0.y + a1.y) + (a2.y + a3.y);
        a.z = (a0.z + a1.z) + (a2.z + a3.z);
        a.w = (a0.w + a1.w) + (a2.w + a3.w);
        int e = blockIdx.x * 64 + tid;
        int nr = e / (PC/4);
        int cc = (e - nr*(PC/4)) * 4;
        float4 vb = *(const float4*)&lb[cc];
        float4 vg = *(const float4*)&lgam[cc];
        float4 vt = *(const float4*)&lbet[cc];
        float4 vm = *(const float4*)&lmean[cc];
        float4 vv = *(const float4*)&lvar[cc];
        float4 r;
        r.x = fmaxf((a.x + vb.x - vm.x) * (vg.x * rsqrtf(vv.x + BN_EPS)) + vt.x, 0.f);
        r.y = fmaxf((a.y + vb.y - vm.y) * (vg.y * rsqrtf(vv.y + BN_EPS)) + vt.y, 0.f);
        r.z = fmaxf((a.z + vb.z - vm.z) * (vg.z * rsqrtf(vv.z + BN_EPS)) + vt.z, 0.f);
        r.w = fmaxf((a.w + vb.w - vm.w) * (vg.w * rsqrtf(vv.w + BN_EPS)) + vt.w, 0.f);
        *(float4*)&g_cat[(size_t)nr*CM + cc] = r;
    }
}

// ---------------------------------------------------------------------------
// Kernel 4a: merge epilogue phase A — reduce partials, BN, ReLU; unscaled y
// to out; per-(n,tile) sq-sums to g_ss.  grid = (4, 64) x 256
// ---------------------------------------------------------------------------
__global__ __launch_bounds__(256) void epi_mergeA(
    const float* __restrict__ mb,   const float* __restrict__ mgam,
    const float* __restrict__ mbet, const float* __restrict__ mmean,
    const float* __restrict__ mvar, float* __restrict__ out)
{
    int tile = blockIdx.x, nrow = blockIdx.y;
    int tid  = threadIdx.x, lane = tid & 31, warp = tid >> 5;
    int c = tile*512 + tid*2;

    float2 a = make_float2(0.f, 0.f);
    #pragma unroll
    for (int ks = 0; ks < KSM; ++ks) {
        float2 t = *(const float2*)&g_mpart[((size_t)ks*NN + nrow)*CC + c];
        a.x += t.x; a.y += t.y;
    }
    float2 vb = *(const float2*)&mb[c];
    float2 vg = *(const float2*)&mgam[c];
    float2 vt = *(const float2*)&mbet[c];
    float2 vm = *(const float2*)&mmean[c];
    float2 vv = *(const float2*)&mvar[c];
    float y0 = fmaxf((a.x + vb.x - vm.x) * (vg.x * rsqrtf(vv.x + BN_EPS)) + vt.x, 0.f);
    float y1 = fmaxf((a.y + vb.y - vm.y) * (vg.y * rsqrtf(vv.y + BN_EPS)) + vt.y, 0.f);
    *(float2*)&out[(size_t)nrow*CC + c] = make_float2(y0, y1);

    float ss = y0*y0 + y1*y1;
    #pragma unroll
    for (int o = 16; o > 0; o >>= 1)
        ss += __shfl_xor_sync(0xffffffffu, ss, o);
    __shared__ float sw[8];
    if (lane == 0) sw[warp] = ss;
    __syncthreads();
    if (tid == 0) {
        float t = 0.f;
        #pragma unroll
        for (int w = 0; w < 8; ++w) t += sw[w];
        g_ss[nrow*4 + tile] = t;
    }
}

// ---------------------------------------------------------------------------
// Kernel 4b: merge epilogue phase B — L2-normalize in place. grid = 64 x 256
// ---------------------------------------------------------------------------
__global__ __launch_bounds__(256) void epi_mergeB(float* __restrict__ out)
{
    int nrow = blockIdx.x, tid = threadIdx.x;
    float ssum = (g_ss[nrow*4+0] + g_ss[nrow*4+1]) + (g_ss[nrow*4+2] + g_ss[nrow*4+3]);
    float inv = 1.0f / fmaxf(sqrtf(ssum), 1e-12f);
    #pragma unroll
    for (int h = 0; h < 2; ++h) {
        size_t idx = (size_t)nrow*CC + h*1024 + tid*4;
        float4 v = *(float4*)&out[idx];
        v.x *= inv; v.y *= inv; v.z *= inv; v.w *= inv;
        *(float4*)&out[idx] = v;
    }
}

// ---------------------------------------------------------------------------
// Launch
// ---------------------------------------------------------------------------
extern "C" void kernel_launch(void* const* d_in, const int* in_sizes, int n_in,
                              void* d_out, int out_size)
{
    const float* x        = (const float*)d_in[0];
    const float* poses    = (const float*)d_in[1];
    const float* local_w  = (const float*)d_in[2];
    const float* local_b  = (const float*)d_in[3];
    const float* local_g  = (const float*)d_in[4];
    const float* local_be = (const float*)d_in[5];
    const float* local_m  = (const float*)d_in[6];
    const float* local_v  = (const float*)d_in[7];
    const float* merge_w  = (const float*)d_in[8];
    const float* merge_b  = (const float*)d_in[9];
    const float* merge_g  = (const float*)d_in[10];
    const float* merge_be = (const float*)d_in[11];
    const float* merge_m  = (const float*)d_in[12];
    const float* merge_v  = (const float*)d_in[13];
    float* out = (float*)d_out;

    cudaFuncSetAttribute(wgemm<0>, cudaFuncAttributeMaxDynamicSharedMemorySize, SMEMG);
    cudaFuncSetAttribute(wgemm<1>, cudaFuncAttributeMaxDynamicSharedMemorySize, SMEMG);

    pool_kernel<<<dim3(CC/256, NN), 256>>>(x, poses);
    wgemm<0><<<dim3(PC/128, KSL), 256, SMEMG>>>(local_w);
    epi_local<<<320, 256>>>(local_b, local_g, local_be, local_m, local_v);
    wgemm<1><<<dim3(CC/128, KSM), 256, SMEMG>>>(merge_w);
    epi_mergeA<<<dim3(4, NN), 256>>>(merge_b, merge_g, merge_be, merge_m, merge_v, out);
    epi_mergeB<<<NN, 256>>>(out);
}

// round 13
// speedup vs baseline: 1.0144x; 1.0144x over previous
#include <cuda_runtime.h>
#include <cuda_bf16.h>
#include <math.h>
#include <cstdint>

// ---------------------------------------------------------------------------
// Problem constants
// ---------------------------------------------------------------------------
#define NN 64
#define CC 2048
#define HH 24
#define WW 12
#define PP 5
#define CLK 256
#define HW  (HH*WW)      // 288
#define PC  (PP*CLK)     // 1280
#define CM  (CC+PC)      // 3328
#define KSL 32           // split-K local  (kchunk 64, 1 stage)
#define KSM 26           // split-K merge  (kchunk 128, 2 stages)
#define BN_EPS 1e-5f

// ---------------------------------------------------------------------------
// Scratch
// ---------------------------------------------------------------------------
__device__ float g_avg[PP*NN*CC];
__device__ float g_cat[NN*CM];
__device__ float g_lpart[KSL*NN*PC];
__device__ float g_mpart[KSM*NN*CC];
__device__ float g_ss[NN*4];

// ---------------------------------------------------------------------------
// PTX helpers (baseline instructions only; NO tcgen05)
// ---------------------------------------------------------------------------
__device__ __forceinline__ uint32_t smem_u32(const void* p) {
    uint32_t a;
    asm("{ .reg .u64 t; cvta.to.shared.u64 t, %1; cvt.u32.u64 %0, t; }" : "=r"(a) : "l"(p));
    return a;
}
__device__ __forceinline__ void ldsm4(uint32_t* r, uint32_t addr) {
    asm volatile("ldmatrix.sync.aligned.m8n8.x4.shared.b16 {%0,%1,%2,%3}, [%4];"
        : "=r"(r[0]), "=r"(r[1]), "=r"(r[2]), "=r"(r[3]) : "r"(addr));
}
__device__ __forceinline__ void mma_bf16(float* d, const uint32_t* a,
                                         uint32_t b0, uint32_t b1) {
    asm volatile(
        "mma.sync.aligned.m16n8k16.row.col.f32.bf16.bf16.f32 "
        "{%0,%1,%2,%3}, {%4,%5,%6,%7}, {%8,%9}, {%0,%1,%2,%3};"
        : "+f"(d[0]), "+f"(d[1]), "+f"(d[2]), "+f"(d[3])
        : "r"(a[0]), "r"(a[1]), "r"(a[2]), "r"(a[3]), "r"(b0), "r"(b1));
}
// pack two fp32 -> bf16x2 (round-to-nearest)
__device__ __forceinline__ uint32_t cvt2(float lo, float hi) {
    uint32_t r;
    asm("cvt.rn.bf16x2.f32 %0, %1, %2;" : "=r"(r) : "f"(hi), "f"(lo));
    return r;
}
// residual pair given packed hi pair
__device__ __forceinline__ uint32_t resid2(uint32_t hpack, float lo, float hi) {
    float rlo = lo - __uint_as_float(hpack << 16);
    float rhi = hi - __uint_as_float(hpack & 0xFFFF0000u);
    return cvt2(rlo, rhi);
}
// fp32 -> bf16 hi/lo split of 8 contiguous values; 16B store per plane at sw.
__device__ __forceinline__ void cvt_store8(const float* __restrict__ src,
                                           char* hip, char* lop, uint32_t sw)
{
    float4 f0 = *(const float4*)src;
    float4 f1 = *(const float4*)(src + 4);
    uint4 vh, vl;
    vh.x = cvt2(f0.x, f0.y);  vl.x = resid2(vh.x, f0.x, f0.y);
    vh.y = cvt2(f0.z, f0.w);  vl.y = resid2(vh.y, f0.z, f0.w);
    vh.z = cvt2(f1.x, f1.y);  vl.z = resid2(vh.z, f1.x, f1.y);
    vh.w = cvt2(f1.z, f1.w);  vl.w = resid2(vh.w, f1.z, f1.w);
    *(uint4*)(hip + sw) = vh;
    *(uint4*)(lop + sw) = vl;
}

// ---------------------------------------------------------------------------
// Kernel 1: fused boxes + pooling + global max (R10 form — best measured).
// grid = (8 ctiles, 64 n), 256 threads
// ---------------------------------------------------------------------------
__global__ __launch_bounds__(256) void pool_kernel(const float* __restrict__ x,
                                                   const float* __restrict__ poses)
{
    int n   = blockIdx.y;
    int c0  = blockIdx.x * 256;
    int tid = threadIdx.x, warp = tid >> 5, lane = tid & 31;

    __shared__ int   s_box[PP][4];
    __shared__ float s_inv[PP];
    __shared__ float s_avg[PP][256];
    __shared__ float s_max[256];
    __shared__ float s_red[8][32][25];

    if (tid < PP) {
        int p = tid;
        const float* kp = poses + ((long long)n*17 + p*4)*4;
        float kx = kp[0], ky = kp[1], kz = kp[2];
        float bx  = fminf(fmaxf(kx - 0.25f, 0.0f), 0.75f) * kz;
        float by  = fminf(fmaxf(ky - 0.25f, 0.0f), 0.75f) * kz;
        float bwh = 0.5f * kz;
        int xs = max(0,      (int)rintf((float)WW * bx));
        int xe = min(WW - 1, (int)rintf((float)WW * (bx + bwh)));
        int ys = max(0,      (int)rintf((float)HH * by));
        int ye = min(HH - 1, (int)rintf((float)HH * (by + bwh)));
        s_box[p][0] = xs; s_box[p][1] = xe; s_box[p][2] = ys; s_box[p][3] = ye;
        int area = (ye - ys) * (xe - xs);
        s_inv[p] = (area > 0) ? (1.0f / (float)area) : 1.0f;
    }
    __syncthreads();

    // per-lane 5-bit masks for hw = lane + 32k
    unsigned mk[9];
    #pragma unroll
    for (int k = 0; k < 9; ++k) {
        int hw = lane + 32*k;
        int h = hw / WW, w = hw % WW;
        unsigned m = 0;
        #pragma unroll
        for (int p = 0; p < PP; ++p) {
            bool in = (h >= s_box[p][2]) && (h < s_box[p][3]) &&
                      (w >= s_box[p][0]) && (w < s_box[p][1]);
            if (in) m |= (1u << p);
        }
        mk[k] = m;
    }

    #pragma unroll 1
    for (int g = 0; g < 8; ++g) {
        int c = c0 + warp*32 + g*4;
        const float* b = x + ((size_t)(n*CC + c))*HW + lane;
        float v[4][9];
        #pragma unroll
        for (int q = 0; q < 4; ++q)
            #pragma unroll
            for (int k = 0; k < 9; ++k)
                v[q][k] = __ldg(b + (size_t)q*HW + 32*k);

        float s[4][PP];
        float mx[4];
        #pragma unroll
        for (int q = 0; q < 4; ++q) {
            mx[q] = -3.402823466e38f;
            #pragma unroll
            for (int p = 0; p < PP; ++p) s[q][p] = 0.f;
        }
        #pragma unroll
        for (int k = 0; k < 9; ++k) {
            unsigned m = mk[k];
            #pragma unroll
            for (int q = 0; q < 4; ++q) mx[q] = fmaxf(mx[q], v[q][k]);
            #pragma unroll
            for (int p = 0; p < PP; ++p) {
                if (m & (1u << p)) {
                    s[0][p] += v[0][k]; s[1][p] += v[1][k];
                    s[2][p] += v[2][k]; s[3][p] += v[3][k];
                }
            }
        }
        // smem transpose reduce
        #pragma unroll
        for (int q = 0; q < 4; ++q) {
            #pragma unroll
            for (int p = 0; p < PP; ++p) s_red[warp][lane][q*6 + p] = s[q][p];
            s_red[warp][lane][q*6 + 5] = mx[q];
        }
        __syncwarp();
        if (lane < 24) {
            int q = lane / 6, r = lane - q*6;
            int ch = warp*32 + g*4 + q;
            if (r < 5) {
                float a0 = 0.f, a1 = 0.f, a2 = 0.f, a3 = 0.f;
                #pragma unroll
                for (int l = 0; l < 32; l += 4) {
                    a0 += s_red[warp][l+0][lane];
                    a1 += s_red[warp][l+1][lane];
                    a2 += s_red[warp][l+2][lane];
                    a3 += s_red[warp][l+3][lane];
                }
                s_avg[r][ch] = (a0 + a1) + (a2 + a3);
            } else {
                float m0 = s_red[warp][0][lane];
                #pragma unroll
                for (int l = 1; l < 32; ++l) m0 = fmaxf(m0, s_red[warp][l][lane]);
                s_max[ch] = m0;
            }
        }
        __syncwarp();
    }
    __syncthreads();
    int c = c0 + tid;
    #pragma unroll
    for (int p = 0; p < PP; ++p)
        g_avg[((size_t)p*NN + n)*CC + c] = s_avg[p][tid] * s_inv[p];
    g_cat[n*CM + PC + c] = s_max[tid];
}

// ---------------------------------------------------------------------------
// Kernel 2: warp-MMA bf16x3 split-K GEMM, 64x256 block tile.
// 8 warps as 2 row-groups x 4 col-groups; warp tile 32x64 -> B re-read x2,
// A re-read x4 (was x4/x2 with 16x64): ~31% less L1 traffic per MAC.
// smem: A_hi 0, A_lo 8K, B_hi 16K, B_lo 48K  (80KB total, 2 CTAs/SM)
// MODE 0: local grid (5, 32), 1 stage.  MODE 1: merge grid (8, 26), 2 stages.
// ---------------------------------------------------------------------------
#define SM_BHI 16384
#define SM_BLO 49152
#define SMEMG  (81920 + 256)

template<int MODE>
__global__ __launch_bounds__(256, 2) void wgemm(const float* __restrict__ Bw)
{
    constexpr int LDAB = MODE ? CM : CC;
    constexpr int NTOT = MODE ? CC : PC;
    constexpr int KSg  = MODE ? KSM : KSL;
    constexpr int KCH  = (MODE ? CM : CC) / KSg;   // 128 / 64
    constexpr int NST  = KCH / 64;                 // 2 / 1

    extern __shared__ char smraw[];
    uint32_t rawu  = smem_u32(smraw);
    uint32_t sbase = (rawu + 127) & ~127u;
    char* sm = smraw + (sbase - rawu);

    int tid = threadIdx.x, wid = tid >> 5, lane = tid & 31;
    int ct = blockIdx.x, ks = blockIdx.y;

    const float* Ab = MODE ? g_cat : (g_avg + (size_t)ct * NN * CC);
    const float* Bb = Bw + (size_t)ct * 256 * LDAB;
    float* Cp = MODE ? g_mpart : g_lpart;
    int colbase = ct * 256;

    int rg  = wid & 1;                 // row group (32 rows)
    int cg  = wid >> 1;                // col group (64 cols)
    int r0  = rg * 32;
    int c0w = cg * 64;

    int aRowBase  = r0 + (lane & 15);
    uint32_t aK   = (uint32_t)((lane >> 4) & 1) * 16;
    int bnrel     = (lane & 7) + ((lane >> 4) << 3);
    uint32_t bK   = (uint32_t)((lane >> 3) & 1) * 16;

    float acc[2][8][4];
    #pragma unroll
    for (int m = 0; m < 2; ++m)
        #pragma unroll
        for (int t = 0; t < 8; ++t)
            { acc[m][t][0]=acc[m][t][1]=acc[m][t][2]=acc[m][t][3]=0.f; }

    int kbeg = ks * KCH;
    #pragma unroll 1
    for (int st = 0; st < NST; ++st) {
        int k0 = kbeg + st * 64;
        // ---- stage A (64x64): 512 groups, 2 per thread
        #pragma unroll
        for (int i = 0; i < 2; ++i) {
            int g = tid + i * 256;
            int r = g >> 3, c = (g & 7) * 8;
            uint32_t off = (uint32_t)r*128 + (((uint32_t)c*2) ^ (((uint32_t)(r&7))<<4));
            cvt_store8(Ab + (size_t)r*LDAB + k0 + c, sm, sm + 8192, off);
        }
        // ---- stage B (256x64): 2048 groups, 8 per thread
        #pragma unroll
        for (int i = 0; i < 8; ++i) {
            int g = tid + i * 256;
            int r = g >> 3, c = (g & 7) * 8;
            uint32_t off = (uint32_t)r*128 + (((uint32_t)c*2) ^ (((uint32_t)(r&7))<<4));
            cvt_store8(Bb + (size_t)r*LDAB + k0 + c, sm + SM_BHI, sm + SM_BLO, off);
        }
        __syncthreads();

        #pragma unroll
        for (int kk = 0; kk < 4; ++kk) {
            uint32_t k2 = (uint32_t)kk * 32;
            uint32_t Ahi[2][4], Alo[2][4];
            #pragma unroll
            for (int m = 0; m < 2; ++m) {
                int ar = aRowBase + m*16;
                uint32_t aoff = (uint32_t)ar*128 +
                                ((k2 + aK) ^ (((uint32_t)(ar & 7)) << 4));
                ldsm4(Ahi[m], sbase + aoff);
                ldsm4(Alo[m], sbase + 8192 + aoff);
            }
            #pragma unroll
            for (int gq = 0; gq < 4; ++gq) {
                int brow = c0w + gq*16 + bnrel;
                uint32_t boff = (uint32_t)brow*128 +
                                ((k2 + bK) ^ (((uint32_t)(brow & 7)) << 4));
                uint32_t Bh[4], Bl[4];
                ldsm4(Bh, sbase + SM_BHI + boff);
                ldsm4(Bl, sbase + SM_BLO + boff);
                #pragma unroll
                for (int m = 0; m < 2; ++m) {
                    #pragma unroll
                    for (int hf = 0; hf < 2; ++hf) {
                        float* d = acc[m][gq*2 + hf];
                        mma_bf16(d, Ahi[m], Bh[hf*2], Bh[hf*2+1]);
                        mma_bf16(d, Ahi[m], Bl[hf*2], Bl[hf*2+1]);
                        mma_bf16(d, Alo[m], Bh[hf*2], Bh[hf*2+1]);
                    }
                }
            }
        }
        if (st + 1 < NST) __syncthreads();
    }

    int grow = lane >> 2, gcol = (lane & 3) * 2;
    #pragma unroll
    for (int m = 0; m < 2; ++m) {
        #pragma unroll
        for (int t = 0; t < 8; ++t) {
            int row = r0 + m*16 + grow;
            int col = colbase + c0w + t*8 + gcol;
            size_t idx0 = ((size_t)ks*NN + row) * NTOT + col;
            size_t idx1 = idx0 + (size_t)8 * NTOT;
            *(float2*)&Cp[idx0] = make_float2(acc[m][t][0], acc[m][t][1]);
            *(float2*)&Cp[idx1] = make_float2(acc[m][t][2], acc[m][t][3]);
        }
    }
}

// ---------------------------------------------------------------------------
// Kernel 3: local epilogue, 4-way ks-split (8 each) + smem combine.
// grid = 320 x 256
// ---------------------------------------------------------------------------
__global__ __launch_bounds__(256) void epi_local(
    const float* __restrict__ lb,   const float* __restrict__ lgam,
    const float* __restrict__ lbet, const float* __restrict__ lmean,
    const float* __restrict__ lvar)
{
    int tid  = threadIdx.x;
    int out  = tid & 63;
    int part = tid >> 6;                     // 0..3 -> ks 8*part..+7
    int e4   = blockIdx.x * 64 + out;
    int nrow = e4 / (PC/4);
    int c4   = (e4 - nrow*(PC/4)) * 4;

    float4 a = make_float4(0.f, 0.f, 0.f, 0.f);
    #pragma unroll
    for (int i = 0; i < 8; ++i) {
        int ks = part*8 + i;
        float4 t = *(const float4*)&g_lpart[((size_t)ks*NN + nrow)*PC + c4];
        a.x += t.x; a.y += t.y; a.z += t.z; a.w += t.w;
    }
    __shared__ float4 sred[4][64];
    sred[part][out] = a;
    __syncthreads();
    if (tid < 64) {
        float4 a0 = sred[0][tid], a1 = sred[1][tid], a2 = sred[2][tid], a3 = sred[3][tid];
        a.x = (a0.x + a1.x) + (a2.x + a3.x);
        a.y = (a0.y + a1.y) + (a2.y + a3.y);
        a.z = (a0.z + a1.z) + (a2.z + a3.z);
        a.w = (a0.w + a1.w) + (a2.w + a3.w);
        int e = blockIdx.x * 64 + tid;
        int nr = e / (PC/4);
        int cc = (e - nr*(PC/4)) * 4;
        float4 vb = *(const float4*)&lb[cc];
        float4 vg = *(const float4*)&lgam[cc];
        float4 vt = *(const float4*)&lbet[cc];
        float4 vm = *(const float4*)&lmean[cc];
        float4 vv = *(const float4*)&lvar[cc];
        float4 r;
        r.x = fmaxf((a.x + vb.x - vm.x) * (vg.x * rsqrtf(vv.x + BN_EPS)) + vt.x, 0.f);
        r.y = fmaxf((a.y + vb.y - vm.y) * (vg.y * rsqrtf(vv.y + BN_EPS)) + vt.y, 0.f);
        r.z = fmaxf((a.z + vb.z - vm.z) * (vg.z * rsqrtf(vv.z + BN_EPS)) + vt.z, 0.f);
        r.w = fmaxf((a.w + vb.w - vm.w) * (vg.w * rsqrtf(vv.w + BN_EPS)) + vt.w, 0.f);
        *(float4*)&g_cat[(size_t)nr*CM + cc] = r;
    }
}

// ---------------------------------------------------------------------------
// Kernel 4a: merge epilogue phase A — reduce partials, BN, ReLU; unscaled y
// to out; per-(n,tile) sq-sums to g_ss.  grid = (4, 64) x 256
// ---------------------------------------------------------------------------
__global__ __launch_bounds__(256) void epi_mergeA(
    const float* __restrict__ mb,   const float* __restrict__ mgam,
    const float* __restrict__ mbet, const float* __restrict__ mmean,
    const float* __restrict__ mvar, float* __restrict__ out)
{
    int tile = blockIdx.x, nrow = blockIdx.y;
    int tid  = threadIdx.x, lane = tid & 31, warp = tid >> 5;
    int c = tile*512 + tid*2;

    float2 a = make_float2(0.f, 0.f);
    #pragma unroll
    for (int ks = 0; ks < KSM; ++ks) {
        float2 t = *(const float2*)&g_mpart[((size_t)ks*NN + nrow)*CC + c];
        a.x += t.x; a.y += t.y;
    }
    float2 vb = *(const float2*)&mb[c];
    float2 vg = *(const float2*)&mgam[c];
    float2 vt = *(const float2*)&mbet[c];
    float2 vm = *(const float2*)&mmean[c];
    float2 vv = *(const float2*)&mvar[c];
    float y0 = fmaxf((a.x + vb.x - vm.x) * (vg.x * rsqrtf(vv.x + BN_EPS)) + vt.x, 0.f);
    float y1 = fmaxf((a.y + vb.y - vm.y) * (vg.y * rsqrtf(vv.y + BN_EPS)) + vt.y, 0.f);
    *(float2*)&out[(size_t)nrow*CC + c] = make_float2(y0, y1);

    float ss = y0*y0 + y1*y1;
    #pragma unroll
    for (int o = 16; o > 0; o >>= 1)
        ss += __shfl_xor_sync(0xffffffffu, ss, o);
    __shared__ float sw[8];
    if (lane == 0) sw[warp] = ss;
    __syncthreads();
    if (tid == 0) {
        float t = 0.f;
        #pragma unroll
        for (int w = 0; w < 8; ++w) t += sw[w];
        g_ss[nrow*4 + tile] = t;
    }
}

// ---------------------------------------------------------------------------
// Kernel 4b: merge epilogue phase B — L2-normalize in place. grid = 64 x 256
// ---------------------------------------------------------------------------
__global__ __launch_bounds__(256) void epi_mergeB(float* __restrict__ out)
{
    int nrow = blockIdx.x, tid = threadIdx.x;
    float ssum = (g_ss[nrow*4+0] + g_ss[nrow*4+1]) + (g_ss[nrow*4+2] + g_ss[nrow*4+3]);
    float inv = 1.0f / fmaxf(sqrtf(ssum), 1e-12f);
    #pragma unroll
    for (int h = 0; h < 2; ++h) {
        size_t idx = (size_t)nrow*CC + h*1024 + tid*4;
        float4 v = *(float4*)&out[idx];
        v.x *= inv; v.y *= inv; v.z *= inv; v.w *= inv;
        *(float4*)&out[idx] = v;
    }
}

// ---------------------------------------------------------------------------
// Launch
// ---------------------------------------------------------------------------
extern "C" void kernel_launch(void* const* d_in, const int* in_sizes, int n_in,
                              void* d_out, int out_size)
{
    const float* x        = (const float*)d_in[0];
    const float* poses    = (const float*)d_in[1];
    const float* local_w  = (const float*)d_in[2];
    const float* local_b  = (const float*)d_in[3];
    const float* local_g  = (const float*)d_in[4];
    const float* local_be = (const float*)d_in[5];
    const float* local_m  = (const float*)d_in[6];
    const float* local_v  = (const float*)d_in[7];
    const float* merge_w  = (const float*)d_in[8];
    const float* merge_b  = (const float*)d_in[9];
    const float* merge_g  = (const float*)d_in[10];
    const float* merge_be = (const float*)d_in[11];
    const float* merge_m  = (const float*)d_in[12];
    const float* merge_v  = (const float*)d_in[13];
    float* out = (float*)d_out;

    cudaFuncSetAttribute(wgemm<0>, cudaFuncAttributeMaxDynamicSharedMemorySize, SMEMG);
    cudaFuncSetAttribute(wgemm<1>, cudaFuncAttributeMaxDynamicSharedMemorySize, SMEMG);

    pool_kernel<<<dim3(CC/256, NN), 256>>>(x, poses);
    wgemm<0><<<dim3(PC/256, KSL), 256, SMEMG>>>(local_w);
    epi_local<<<320, 256>>>(local_b, local_g, local_be, local_m, local_v);
    wgemm<1><<<dim3(CC/256, KSM), 256, SMEMG>>>(merge_w);
    epi_mergeA<<<dim3(4, NN), 256>>>(merge_b, merge_g, merge_be, merge_m, merge_v, out);
    epi_mergeB<<<NN, 256>>>(out);
}

// round 16
// speedup vs baseline: 1.0862x; 1.0708x over previous
#include <cuda_runtime.h>
#include <cuda_bf16.h>
#include <math.h>
#include <cstdint>

// ---------------------------------------------------------------------------
// Problem constants
// ---------------------------------------------------------------------------
#define NN 64
#define CC 2048
#define HH 24
#define WW 12
#define PP 5
#define CLK 256
#define HW  (HH*WW)      // 288
#define PC  (PP*CLK)     // 1280
#define CM  (CC+PC)      // 3328
#define KSL 16           // split-K local  (kchunk 128, 2 stages)
#define KSM 26           // split-K merge  (kchunk 128, 2 stages)
#define BN_EPS 1e-5f

// ---------------------------------------------------------------------------
// Scratch
// ---------------------------------------------------------------------------
__device__ float g_avg[PP*NN*CC];
__device__ float g_cat[NN*CM];
__device__ float g_lpart[KSL*NN*PC];
__device__ float g_mpart[KSM*NN*CC];
__device__ float g_ss[NN*4];

// ---------------------------------------------------------------------------
// PTX helpers (baseline instructions only; NO tcgen05)
// ---------------------------------------------------------------------------
__device__ __forceinline__ uint32_t smem_u32(const void* p) {
    uint32_t a;
    asm("{ .reg .u64 t; cvta.to.shared.u64 t, %1; cvt.u32.u64 %0, t; }" : "=r"(a) : "l"(p));
    return a;
}
__device__ __forceinline__ void ldsm4(uint32_t* r, uint32_t addr) {
    asm volatile("ldmatrix.sync.aligned.m8n8.x4.shared.b16 {%0,%1,%2,%3}, [%4];"
        : "=r"(r[0]), "=r"(r[1]), "=r"(r[2]), "=r"(r[3]) : "r"(addr));
}
__device__ __forceinline__ void mma_bf16(float* d, const uint32_t* a,
                                         uint32_t b0, uint32_t b1) {
    asm volatile(
        "mma.sync.aligned.m16n8k16.row.col.f32.bf16.bf16.f32 "
        "{%0,%1,%2,%3}, {%4,%5,%6,%7}, {%8,%9}, {%0,%1,%2,%3};"
        : "+f"(d[0]), "+f"(d[1]), "+f"(d[2]), "+f"(d[3])
        : "r"(a[0]), "r"(a[1]), "r"(a[2]), "r"(a[3]), "r"(b0), "r"(b1));
}
// pack two fp32 -> bf16x2 (round-to-nearest)
__device__ __forceinline__ uint32_t cvt2(float lo, float hi) {
    uint32_t r;
    asm("cvt.rn.bf16x2.f32 %0, %1, %2;" : "=r"(r) : "f"(hi), "f"(lo));
    return r;
}
// residual pair given packed hi pair
__device__ __forceinline__ uint32_t resid2(uint32_t hpack, float lo, float hi) {
    float rlo = lo - __uint_as_float(hpack << 16);
    float rhi = hi - __uint_as_float(hpack & 0xFFFF0000u);
    return cvt2(rlo, rhi);
}
// convert 2 preloaded float4s -> hi/lo bf16 planes (16B store each) at sw
__device__ __forceinline__ void cvt_store_pair(float4 f0, float4 f1,
                                               char* hip, char* lop, uint32_t sw)
{
    uint4 vh, vl;
    vh.x = cvt2(f0.x, f0.y);  vl.x = resid2(vh.x, f0.x, f0.y);
    vh.y = cvt2(f0.z, f0.w);  vl.y = resid2(vh.y, f0.z, f0.w);
    vh.z = cvt2(f1.x, f1.y);  vl.z = resid2(vh.z, f1.x, f1.y);
    vh.w = cvt2(f1.z, f1.w);  vl.w = resid2(vh.w, f1.z, f1.w);
    *(uint4*)(hip + sw) = vh;
    *(uint4*)(lop + sw) = vl;
}

// ---------------------------------------------------------------------------
// Kernel 1: fused boxes + pooling + global max (best-measured R10 form).
// grid = (8 ctiles, 64 n), 256 threads
// ---------------------------------------------------------------------------
__global__ __launch_bounds__(256) void pool_kernel(const float* __restrict__ x,
                                                   const float* __restrict__ poses)
{
    int n   = blockIdx.y;
    int c0  = blockIdx.x * 256;
    int tid = threadIdx.x, warp = tid >> 5, lane = tid & 31;

    __shared__ int   s_box[PP][4];
    __shared__ float s_inv[PP];
    __shared__ float s_avg[PP][256];
    __shared__ float s_max[256];
    __shared__ float s_red[8][32][25];

    if (tid < PP) {
        int p = tid;
        const float* kp = poses + ((long long)n*17 + p*4)*4;
        float kx = kp[0], ky = kp[1], kz = kp[2];
        float bx  = fminf(fmaxf(kx - 0.25f, 0.0f), 0.75f) * kz;
        float by  = fminf(fmaxf(ky - 0.25f, 0.0f), 0.75f) * kz;
        float bwh = 0.5f * kz;
        int xs = max(0,      (int)rintf((float)WW * bx));
        int xe = min(WW - 1, (int)rintf((float)WW * (bx + bwh)));
        int ys = max(0,      (int)rintf((float)HH * by));
        int ye = min(HH - 1, (int)rintf((float)HH * (by + bwh)));
        s_box[p][0] = xs; s_box[p][1] = xe; s_box[p][2] = ys; s_box[p][3] = ye;
        int area = (ye - ys) * (xe - xs);
        s_inv[p] = (area > 0) ? (1.0f / (float)area) : 1.0f;
    }
    __syncthreads();

    unsigned mk[9];
    #pragma unroll
    for (int k = 0; k < 9; ++k) {
        int hw = lane + 32*k;
        int h = hw / WW, w = hw % WW;
        unsigned m = 0;
        #pragma unroll
        for (int p = 0; p < PP; ++p) {
            bool in = (h >= s_box[p][2]) && (h < s_box[p][3]) &&
                      (w >= s_box[p][0]) && (w < s_box[p][1]);
            if (in) m |= (1u << p);
        }
        mk[k] = m;
    }

    #pragma unroll 1
    for (int g = 0; g < 8; ++g) {
        int c = c0 + warp*32 + g*4;
        const float* b = x + ((size_t)(n*CC + c))*HW + lane;
        float v[4][9];
        #pragma unroll
        for (int q = 0; q < 4; ++q)
            #pragma unroll
            for (int k = 0; k < 9; ++k)
                v[q][k] = __ldg(b + (size_t)q*HW + 32*k);

        float s[4][PP];
        float mx[4];
        #pragma unroll
        for (int q = 0; q < 4; ++q) {
            mx[q] = -3.402823466e38f;
            #pragma unroll
            for (int p = 0; p < PP; ++p) s[q][p] = 0.f;
        }
        #pragma unroll
        for (int k = 0; k < 9; ++k) {
            unsigned m = mk[k];
            #pragma unroll
            for (int q = 0; q < 4; ++q) mx[q] = fmaxf(mx[q], v[q][k]);
            #pragma unroll
            for (int p = 0; p < PP; ++p) {
                if (m & (1u << p)) {
                    s[0][p] += v[0][k]; s[1][p] += v[1][k];
                    s[2][p] += v[2][k]; s[3][p] += v[3][k];
                }
            }
        }
        #pragma unroll
        for (int q = 0; q < 4; ++q) {
            #pragma unroll
            for (int p = 0; p < PP; ++p) s_red[warp][lane][q*6 + p] = s[q][p];
            s_red[warp][lane][q*6 + 5] = mx[q];
        }
        __syncwarp();
        if (lane < 24) {
            int q = lane / 6, r = lane - q*6;
            int ch = warp*32 + g*4 + q;
            if (r < 5) {
                float a0 = 0.f, a1 = 0.f, a2 = 0.f, a3 = 0.f;
                #pragma unroll
                for (int l = 0; l < 32; l += 4) {
                    a0 += s_red[warp][l+0][lane];
                    a1 += s_red[warp][l+1][lane];
                    a2 += s_red[warp][l+2][lane];
                    a3 += s_red[warp][l+3][lane];
                }
                s_avg[r][ch] = (a0 + a1) + (a2 + a3);
            } else {
                float m0 = s_red[warp][0][lane];
                #pragma unroll
                for (int l = 1; l < 32; ++l) m0 = fmaxf(m0, s_red[warp][l][lane]);
                s_max[ch] = m0;
            }
        }
        __syncwarp();
    }
    __syncthreads();
    int c = c0 + tid;
    #pragma unroll
    for (int p = 0; p < PP; ++p)
        g_avg[((size_t)p*NN + n)*CC + c] = s_avg[p][tid] * s_inv[p];
    g_cat[n*CM + PC + c] = s_max[tid];
}

// ---------------------------------------------------------------------------
// Kernel 2: warp-MMA bf16x3 split-K GEMM, 64x128 block tile, BATCHED LDGs.
// All 12 LDG.128s of a stage (A:4, B:8) are issued in ONE register burst
// (MLP=12) before any convert/STS — fix for the measured 1.5 TB/s ceiling.
// A tile 64x64 = 512 groups (2/thread); B tile 128x64 = 1024 groups (4/thread).
// smem: A_hi 0, A_lo 8K, B_hi 16K, B_lo 32K (48KB, 2 CTAs/SM)
// MODE 0: local grid (10, 16).  MODE 1: merge grid (16, 26).  Both: 2 stages.
// ---------------------------------------------------------------------------
#define SMEMG (49152 + 1024)

template<int MODE>
__global__ __launch_bounds__(256, 2) void wgemm(const float* __restrict__ Bw)
{
    constexpr int LDAB = MODE ? CM : CC;
    constexpr int NTOT = MODE ? CC : PC;
    constexpr int KSg  = MODE ? KSM : KSL;
    constexpr int KCH  = (MODE ? CM : CC) / KSg;   // 128 / 128
    constexpr int NST  = KCH / 64;                 // 2 / 2

    extern __shared__ char smraw[];
    uint32_t rawu  = smem_u32(smraw);
    uint32_t sbase = (rawu + 127) & ~127u;
    char* sm = smraw + (sbase - rawu);

    int tid = threadIdx.x, wid = tid >> 5, lane = tid & 31;
    int ct = blockIdx.x, ks = blockIdx.y;

    const float* Ab = MODE ? g_cat : (g_avg + (size_t)(ct >> 1) * NN * CC);
    const float* Bb = MODE ? (Bw + (size_t)ct * 128 * LDAB)
                           : (Bw + (size_t)(ct >> 1) * CLK * CC + (size_t)(ct & 1) * 128 * CC);
    float* Cp = MODE ? g_mpart : g_lpart;
    int colbase = ct * 128;

    int r0  = (wid & 3) * 16;
    int c0w = (wid >> 2) * 64;

    int aRow = r0 + (lane & 15);
    uint32_t aOffBase = (uint32_t)aRow * 128;
    uint32_t aRot     = (uint32_t)(aRow & 7) << 4;
    uint32_t aK       = (uint32_t)(lane >> 4) * 16;
    int bnrel         = (lane & 7) + ((lane >> 4) << 3);
    uint32_t bK       = (uint32_t)((lane >> 3) & 1) * 16;

    float acc[8][4];
    #pragma unroll
    for (int t = 0; t < 8; ++t) { acc[t][0]=acc[t][1]=acc[t][2]=acc[t][3]=0.f; }

    // staging addresses: A 2 groups/thread (64 rows), B 4 groups/thread (128 rows)
    int rA[2], cA[2], rB[4], cB[4];
    uint32_t oA[2], oB[4];
    #pragma unroll
    for (int i = 0; i < 2; ++i) {
        int g = tid + i * 256;                // 0..511
        rA[i] = g >> 3; cA[i] = (g & 7) * 8;  // rows 0..63
        oA[i] = (uint32_t)rA[i]*128 + (((uint32_t)cA[i]*2) ^ (((uint32_t)(rA[i]&7))<<4));
    }
    #pragma unroll
    for (int i = 0; i < 4; ++i) {
        int g = tid + i * 256;                // 0..1023
        rB[i] = g >> 3; cB[i] = (g & 7) * 8;  // rows 0..127
        oB[i] = (uint32_t)rB[i]*128 + (((uint32_t)cB[i]*2) ^ (((uint32_t)(rB[i]&7))<<4));
    }

    int kbeg = ks * KCH;
    #pragma unroll 1
    for (int st = 0; st < NST; ++st) {
        int k0 = kbeg + st * 64;

        // ---- single burst: 12 independent LDG.128 in flight
        float4 fa[4], fb[8];
        #pragma unroll
        for (int i = 0; i < 2; ++i) {
            const float* s = Ab + (size_t)rA[i]*LDAB + k0 + cA[i];
            fa[2*i]   = __ldg((const float4*)s);
            fa[2*i+1] = __ldg((const float4*)(s + 4));
        }
        #pragma unroll
        for (int i = 0; i < 4; ++i) {
            const float* s = Bb + (size_t)rB[i]*LDAB + k0 + cB[i];
            fb[2*i]   = __ldg((const float4*)s);
            fb[2*i+1] = __ldg((const float4*)(s + 4));
        }
        // ---- convert + store after all loads issued
        #pragma unroll
        for (int i = 0; i < 2; ++i)
            cvt_store_pair(fa[2*i], fa[2*i+1], sm, sm + 8192, oA[i]);
        #pragma unroll
        for (int i = 0; i < 4; ++i)
            cvt_store_pair(fb[2*i], fb[2*i+1], sm + 16384, sm + 32768, oB[i]);

        __syncthreads();

        #pragma unroll
        for (int kk = 0; kk < 4; ++kk) {
            uint32_t k2 = (uint32_t)kk * 32;
            uint32_t aoff = aOffBase + ((k2 + aK) ^ aRot);
            uint32_t Ahi[4], Alo[4];
            ldsm4(Ahi, sbase + aoff);
            ldsm4(Alo, sbase + 8192 + aoff);
            #pragma unroll
            for (int gq = 0; gq < 4; ++gq) {
                int brow = c0w + gq*16 + bnrel;
                uint32_t boff = (uint32_t)brow*128 +
                                ((k2 + bK) ^ (((uint32_t)(brow & 7)) << 4));
                uint32_t Bh[4], Bl[4];
                ldsm4(Bh, sbase + 16384 + boff);
                ldsm4(Bl, sbase + 32768 + boff);
                #pragma unroll
                for (int hf = 0; hf < 2; ++hf) {
                    float* d = acc[gq*2 + hf];
                    mma_bf16(d, Ahi, Bh[hf*2], Bh[hf*2+1]);
                    mma_bf16(d, Ahi, Bl[hf*2], Bl[hf*2+1]);
                    mma_bf16(d, Alo, Bh[hf*2], Bh[hf*2+1]);
                }
            }
        }
        if (st + 1 < NST) __syncthreads();
    }

    int grow = lane >> 2, gcol = (lane & 3) * 2;
    #pragma unroll
    for (int t = 0; t < 8; ++t) {
        int col = colbase + c0w + t*8 + gcol;
        size_t idx0 = ((size_t)ks*NN + r0 + grow) * NTOT + col;
        size_t idx1 = idx0 + (size_t)8 * NTOT;
        *(float2*)&Cp[idx0] = make_float2(acc[t][0], acc[t][1]);
        *(float2*)&Cp[idx1] = make_float2(acc[t][2], acc[t][3]);
    }
}

// ---------------------------------------------------------------------------
// Kernel 3: local epilogue, 4-way ks-split (4 each) + smem combine.
// grid = 320 x 256
// ---------------------------------------------------------------------------
__global__ __launch_bounds__(256) void epi_local(
    const float* __restrict__ lb,   const float* __restrict__ lgam,
    const float* __restrict__ lbet, const float* __restrict__ lmean,
    const float* __restrict__ lvar)
{
    int tid  = threadIdx.x;
    int out  = tid & 63;
    int part = tid >> 6;                     // 0..3 -> ks 4*part..+3
    int e4   = blockIdx.x * 64 + out;
    int nrow = e4 / (PC/4);
    int c4   = (e4 - nrow*(PC/4)) * 4;

    float4 a = make_float4(0.f, 0.f, 0.f, 0.f);
    #pragma unroll
    for (int i = 0; i < 4; ++i) {
        int ks = part*4 + i;
        float4 t = *(const float4*)&g_lpart[((size_t)ks*NN + nrow)*PC + c4];
        a.x += t.x; a.y += t.y; a.z += t.z; a.w += t.w;
    }
    __shared__ float4 sred[4][64];
    sred[part][out] = a;
    __syncthreads();
    if (tid < 64) {
        float4 a0 = sred[0][tid], a1 = sred[1][tid], a2 = sred[2][tid], a3 = sred[3][tid];
        a.x = (a0.x + a1.x) + (a2.x + a3.x);
        a.y = (a0.y + a1.y) + (a2.y + a3.y);
        a.z = (a0.z + a1.z) + (a2.z + a3.z);
        a.w = (a0.w + a1.w) + (a2.w + a3.w);
        int e = blockIdx.x * 64 + tid;
        int nr = e / (PC/4);
        int cc = (e - nr*(PC/4)) * 4;
        float4 vb = *(const float4*)&lb[cc];
        float4 vg = *(const float4*)&lgam[cc];
        float4 vt = *(const float4*)&lbet[cc];
        float4 vm = *(const float4*)&lmean[cc];
        float4 vv = *(const float4*)&lvar[cc];
        float4 r;
        r.x = fmaxf((a.x + vb.x - vm.x) * (vg.x * rsqrtf(vv.x + BN_EPS)) + vt.x, 0.f);
        r.y = fmaxf((a.y + vb.y - vm.y) * (vg.y * rsqrtf(vv.y + BN_EPS)) + vt.y, 0.f);
        r.z = fmaxf((a.z + vb.z - vm.z) * (vg.z * rsqrtf(vv.z + BN_EPS)) + vt.z, 0.f);
        r.w = fmaxf((a.w + vb.w - vm.w) * (vg.w * rsqrtf(vv.w + BN_EPS)) + vt.w, 0.f);
        *(float4*)&g_cat[(size_t)nr*CM + cc] = r;
    }
}

// ---------------------------------------------------------------------------
// Kernel 4a: merge epilogue phase A — reduce partials, BN, ReLU; unscaled y
// to out; per-(n,tile) sq-sums to g_ss.  grid = (4, 64) x 256
// ---------------------------------------------------------------------------
__global__ __launch_bounds__(256) void epi_mergeA(
    const float* __restrict__ mb,   const float* __restrict__ mgam,
    const float* __restrict__ mbet, const float* __restrict__ mmean,
    const float* __restrict__ mvar, float* __restrict__ out)
{
    int tile = blockIdx.x, nrow = blockIdx.y;
    int tid  = threadIdx.x, lane = tid & 31, warp = tid >> 5;
    int c = tile*512 + tid*2;

    float2 a = make_float2(0.f, 0.f);
    #pragma unroll
    for (int ks = 0; ks < KSM; ++ks) {
        float2 t = *(const float2*)&g_mpart[((size_t)ks*NN + nrow)*CC + c];
        a.x += t.x; a.y += t.y;
    }
    float2 vb = *(const float2*)&mb[c];
    float2 vg = *(const float2*)&mgam[c];
    float2 vt = *(const float2*)&mbet[c];
    float2 vm = *(const float2*)&mmean[c];
    float2 vv = *(const float2*)&mvar[c];
    float y0 = fmaxf((a.x + vb.x - vm.x) * (vg.x * rsqrtf(vv.x + BN_EPS)) + vt.x, 0.f);
    float y1 = fmaxf((a.y + vb.y - vm.y) * (vg.y * rsqrtf(vv.y + BN_EPS)) + vt.y, 0.f);
    *(float2*)&out[(size_t)nrow*CC + c] = make_float2(y0, y1);

    float ss = y0*y0 + y1*y1;
    #pragma unroll
    for (int o = 16; o > 0; o >>= 1)
        ss += __shfl_xor_sync(0xffffffffu, ss, o);
    __shared__ float sw[8];
    if (lane == 0) sw[warp] = ss;
    __syncthreads();
    if (tid == 0) {
        float t = 0.f;
        #pragma unroll
        for (int w = 0; w < 8; ++w) t += sw[w];
        g_ss[nrow*4 + tile] = t;
    }
}

// ---------------------------------------------------------------------------
// Kernel 4b: merge epilogue phase B — L2-normalize in place. grid = 64 x 256
// ---------------------------------------------------------------------------
__global__ __launch_bounds__(256) void epi_mergeB(float* __restrict__ out)
{
    int nrow = blockIdx.x, tid = threadIdx.x;
    float ssum = (g_ss[nrow*4+0] + g_ss[nrow*4+1]) + (g_ss[nrow*4+2] + g_ss[nrow*4+3]);
    float inv = 1.0f / fmaxf(sqrtf(ssum), 1e-12f);
    #pragma unroll
    for (int h = 0; h < 2; ++h) {
        size_t idx = (size_t)nrow*CC + h*1024 + tid*4;
        float4 v = *(float4*)&out[idx];
        v.x *= inv; v.y *= inv; v.z *= inv; v.w *= inv;
        *(float4*)&out[idx] = v;
    }
}

// ---------------------------------------------------------------------------
// Launch
// ---------------------------------------------------------------------------
extern "C" void kernel_launch(void* const* d_in, const int* in_sizes, int n_in,
                              void* d_out, int out_size)
{
    const float* x        = (const float*)d_in[0];
    const float* poses    = (const float*)d_in[1];
    const float* local_w  = (const float*)d_in[2];
    const float* local_b  = (const float*)d_in[3];
    const float* local_g  = (const float*)d_in[4];
    const float* local_be = (const float*)d_in[5];
    const float* local_m  = (const float*)d_in[6];
    const float* local_v  = (const float*)d_in[7];
    const float* merge_w  = (const float*)d_in[8];
    const float* merge_b  = (const float*)d_in[9];
    const float* merge_g  = (const float*)d_in[10];
    const float* merge_be = (const float*)d_in[11];
    const float* merge_m  = (const float*)d_in[12];
    const float* merge_v  = (const float*)d_in[13];
    float* out = (float*)d_out;

    cudaFuncSetAttribute(wgemm<0>, cudaFuncAttributeMaxDynamicSharedMemorySize, SMEMG);
    cudaFuncSetAttribute(wgemm<1>, cudaFuncAttributeMaxDynamicSharedMemorySize, SMEMG);

    pool_kernel<<<dim3(CC/256, NN), 256>>>(x, poses);
    wgemm<0><<<dim3(PC/128, KSL), 256, SMEMG>>>(local_w);
    epi_local<<<320, 256>>>(local_b, local_g, local_be, local_m, local_v);
    wgemm<1><<<dim3(CC/128, KSM), 256, SMEMG>>>(merge_w);
    epi_mergeA<<<dim3(4, NN), 256>>>(merge_b, merge_g, merge_be, merge_m, merge_v, out);
    epi_mergeB<<<NN, 256>>>(out);
}